// round 6
// baseline (speedup 1.0000x reference)
#include <cuda_runtime.h>

#define NN  50000
#define NC  256
#define DD  64
#define HH  128
#define EVV 800000
#define EVC 400000
#define NE  (EVV + EVC)

#define CAPVV 64                  // max in-degree stored (Poisson mean 16)
#define CAPVC 32                  // max in-degree stored (Poisson mean 8)

#define FILL_BLOCKS 128
#define VMLP_BLOCKS 160
#define CMLP_BLOCKS 8
#define FUSED_GRID  (FILL_BLOCKS + VMLP_BLOCKS + CMLP_BLOCKS)   // 296 = 148*2
#define NTILES_V    1563          // ceil(50000/32)

typedef unsigned long long ull;

// ---------------- scratch (device globals; zero-initialized at load) --------
__device__ float g_yv[NN * DD];          // per-vertex messages, 12.8 MB
__device__ float g_yc[NC * DD];          // per-color messages, 64 KB
__device__ int   d_cnt_vv[NN];           // in-degree counters (self-cleaned)
__device__ int   d_cnt_vc[NN];
__device__ int   d_slot_vv[NN * CAPVV];  // padded src lists, 12.8 MB
__device__ int   d_slot_vc[NN * CAPVC];  // 6.4 MB

// ---------------- f32x2 helpers --------------------------------------------
__device__ __forceinline__ ull pk2(float lo, float hi) {
    ull r; asm("mov.b64 %0, {%1, %2};" : "=l"(r) : "f"(lo), "f"(hi)); return r;
}
__device__ __forceinline__ void upk2(ull v, float& lo, float& hi) {
    asm("mov.b64 {%0, %1}, %2;" : "=f"(lo), "=f"(hi) : "l"(v));
}
__device__ __forceinline__ ull ffma2(ull a, ull b, ull c) {
    ull d; asm("fma.rn.f32x2 %0, %1, %2, %3;" : "=l"(d) : "l"(a), "l"(b), "l"(c)); return d;
}
__device__ __forceinline__ ull fadd2(ull a, ull b) {
    ull d; asm("add.rn.f32x2 %0, %1, %2;" : "=l"(d) : "l"(a), "l"(b)); return d;
}

// ---------------------------------------------------------------------------
// Fused kernel, three block roles (all resident in one wave):
//   blocks [0, 128)    : edge fill  -> padded slot lists + counters
//   blocks [128, 288)  : vertex MLP -> g_yv   (FFMA2, weights in SMEM)
//   blocks [288, 296)  : color MLP  -> g_yc
// Fill is latency/atomic-bound, MLP is FMA-issue-bound: they overlap.
// ---------------------------------------------------------------------------
__global__ void __launch_bounds__(256, 2) fused_kernel(
    const float* __restrict__ x_v,
    const float* __restrict__ x_c,
    const float* __restrict__ W1v, const float* __restrict__ b1v,
    const float* __restrict__ W2v, const float* __restrict__ b2v,
    const float* __restrict__ W1c, const float* __restrict__ b1c,
    const float* __restrict__ W2c, const float* __restrict__ b2c,
    const int* __restrict__ src_vv, const int* __restrict__ dst_vv,
    const int* __restrict__ src_vc, const int* __restrict__ dst_vc)
{
    const int t = threadIdx.x;

    // ---------------- fill role ----------------
    if (blockIdx.x < FILL_BLOCKS) {
        const int g = blockIdx.x * 256 + t;
        const int stride = FILL_BLOCKS * 256;
        for (int i = g; i < EVV; i += stride) {
            const int d = dst_vv[i];
            const int p = atomicAdd(&d_cnt_vv[d], 1);
            if (p < CAPVV) d_slot_vv[d * CAPVV + p] = src_vv[i];
        }
        for (int i = g; i < EVC; i += stride) {
            const int d = dst_vc[i];
            const int p = atomicAdd(&d_cnt_vc[d], 1);
            if (p < CAPVC) d_slot_vc[d * CAPVC + p] = src_vc[i];
        }
        return;
    }

    // ---------------- MLP roles ----------------
    extern __shared__ float sm[];
    float* W1s = sm;                     // [64][128]
    float* W2s = W1s + DD * HH;          // [128][64]
    float* b1s = W2s + HH * DD;          // [128]
    float* b2s = b1s + HH;               // [64]
    float* xs  = b2s + DD;               // [64][33]  x transposed (padded)
    ull*   hs  = (ull*)(xs + DD * 33);   // [128][33] h duplicated pairs

    const int lane = t & 31;
    const int warp = t >> 5;

    const bool is_color = (blockIdx.x >= FILL_BLOCKS + VMLP_BLOCKS);
    const float *X, *W1, *B1, *W2, *B2;
    float* Y;
    int tile0, tstride, ntile, nrows;
    if (!is_color) {
        X = x_v; Y = g_yv; W1 = W1v; B1 = b1v; W2 = W2v; B2 = b2v;
        tile0 = blockIdx.x - FILL_BLOCKS; tstride = VMLP_BLOCKS;
        ntile = NTILES_V; nrows = NN;
    } else {
        X = x_c; Y = g_yc; W1 = W1c; B1 = b1c; W2 = W2c; B2 = b2c;
        tile0 = blockIdx.x - FILL_BLOCKS - VMLP_BLOCKS; tstride = CMLP_BLOCKS;
        ntile = 8; nrows = NC;
    }

    // cache weights in SMEM (once per block)
    {
        const float4* s1 = (const float4*)W1;
        float4* d1 = (float4*)W1s;
        for (int i = t; i < DD * HH / 4; i += 256) d1[i] = s1[i];
        const float4* s2 = (const float4*)W2;
        float4* d2 = (float4*)W2s;
        for (int i = t; i < HH * DD / 4; i += 256) d2[i] = s2[i];
        if (t < HH) b1s[t] = B1[t];
        if (t < DD) b2s[t] = B2[t];
    }

    for (int tile = tile0; tile < ntile; tile += tstride) {
        const int row0 = tile * 32;
        __syncthreads();   // weights visible / previous tile done with buffers

        // load x tile (32 rows x 64) transposed into xs[k][row]
        {
            const int r = t >> 3;       // 0..31
            const int q = t & 7;
            const int row = row0 + r;
#pragma unroll
            for (int h = 0; h < 2; h++) {
                const int q4 = q + 8 * h;        // 0..15
                float4 v = make_float4(0.f, 0.f, 0.f, 0.f);
                if (row < nrows) v = ((const float4*)X)[row * 16 + q4];
                xs[(4 * q4 + 0) * 33 + r] = v.x;
                xs[(4 * q4 + 1) * 33 + r] = v.y;
                xs[(4 * q4 + 2) * 33 + r] = v.z;
                xs[(4 * q4 + 3) * 33 + r] = v.w;
            }
        }
        __syncthreads();

        // phase 1: h[row][c] = relu(x@W1+b1); row = lane, warp covers 16 cols
        {
            const int c0 = warp * 16;
            ull acc[8];
#pragma unroll
            for (int p = 0; p < 8; p++)
                acc[p] = *(const ull*)(b1s + c0 + 2 * p);
#pragma unroll 4
            for (int k = 0; k < DD; k++) {
                const float xv = xs[k * 33 + lane];
                const ull xp = pk2(xv, xv);
                const ull* wrow = (const ull*)(W1s + k * HH + c0);
#pragma unroll
                for (int p = 0; p < 8; p++)
                    acc[p] = ffma2(wrow[p], xp, acc[p]);
            }
#pragma unroll
            for (int p = 0; p < 8; p++) {
                float lo, hi; upk2(acc[p], lo, hi);
                lo = fmaxf(lo, 0.f); hi = fmaxf(hi, 0.f);
                hs[(c0 + 2 * p + 0) * 33 + lane] = pk2(lo, lo);
                hs[(c0 + 2 * p + 1) * 33 + lane] = pk2(hi, hi);
            }
        }
        __syncthreads();

        // phase 2: y[row][c] = h@W2+b2; row = lane, warp covers 8 cols
        {
            const int c0 = warp * 8;
            ull acc[4];
#pragma unroll
            for (int p = 0; p < 4; p++)
                acc[p] = *(const ull*)(b2s + c0 + 2 * p);
#pragma unroll 4
            for (int j = 0; j < HH; j++) {
                const ull hp = hs[j * 33 + lane];
                const ull* wrow = (const ull*)(W2s + j * DD + c0);
#pragma unroll
                for (int p = 0; p < 4; p++)
                    acc[p] = ffma2(wrow[p], hp, acc[p]);
            }
            const int row = row0 + lane;
            if (row < nrows) {
                float a0, a1, a2, a3, a4, a5, a6, a7;
                upk2(acc[0], a0, a1); upk2(acc[1], a2, a3);
                upk2(acc[2], a4, a5); upk2(acc[3], a6, a7);
                float4* yp = (float4*)(Y + row * DD + c0);
                yp[0] = make_float4(a0, a1, a2, a3);
                yp[1] = make_float4(a4, a5, a6, a7);
            }
        }
    }
}

// ---------------------------------------------------------------------------
// Gather: one warp per vertex, lane = 8B chunk of the 256B row.
//   acc = x_v[v] + sum y_v[slots_vv] + sum y_c[slots_vc]; out = relu(acc).
// Src lists read once per 32 edges (coalesced) and shfl-broadcast.
// Re-zeroes the counters for the next graph replay.
// ---------------------------------------------------------------------------
__global__ void __launch_bounds__(256) gather_kernel(
    const float* __restrict__ x_v, float* __restrict__ out)
{
    const int v = blockIdx.x * 8 + (threadIdx.x >> 5);   // grid*8 == NN
    const int lane = threadIdx.x & 31;

    ull acc = ((const ull*)x_v)[v * 32 + lane];

    // vertex->vertex in-edges
    {
        int cnt = d_cnt_vv[v];
        if (cnt > CAPVV) cnt = CAPVV;
        const int* slots = d_slot_vv + v * CAPVV;
        const ull* yv = (const ull*)g_yv;
        for (int base = 0; base < cnt; base += 32) {
            const int n = min(32, cnt - base);
            const int s_my = (lane < n) ? slots[base + lane] : 0;
            int i = 0;
            for (; i + 8 <= n; i += 8) {
                ull tt[8];
#pragma unroll
                for (int j = 0; j < 8; j++) {
                    const int s = __shfl_sync(0xffffffffu, s_my, i + j);
                    tt[j] = __ldcs(yv + s * 32 + lane);
                }
#pragma unroll
                for (int j = 0; j < 8; j++) acc = fadd2(acc, tt[j]);
            }
            for (; i < n; i++) {
                const int s = __shfl_sync(0xffffffffu, s_my, i);
                acc = fadd2(acc, __ldcs(yv + s * 32 + lane));
            }
        }
    }

    // color->vertex in-edges (y_c is 64 KB, stays L1-hot)
    {
        int cnt = d_cnt_vc[v];
        if (cnt > CAPVC) cnt = CAPVC;
        const int* slots = d_slot_vc + v * CAPVC;
        const ull* yc = (const ull*)g_yc;
        for (int base = 0; base < cnt; base += 32) {
            const int n = min(32, cnt - base);
            const int s_my = (lane < n) ? slots[base + lane] : 0;
            int i = 0;
            for (; i + 4 <= n; i += 4) {
                ull tt[4];
#pragma unroll
                for (int j = 0; j < 4; j++) {
                    const int s = __shfl_sync(0xffffffffu, s_my, i + j);
                    tt[j] = __ldg(yc + s * 32 + lane);
                }
#pragma unroll
                for (int j = 0; j < 4; j++) acc = fadd2(acc, tt[j]);
            }
            for (; i < n; i++) {
                const int s = __shfl_sync(0xffffffffu, s_my, i);
                acc = fadd2(acc, __ldg(yc + s * 32 + lane));
            }
        }
    }

    // self-clean counters so the next replay starts from zero
    if (lane == 0) {
        d_cnt_vv[v] = 0;
        d_cnt_vc[v] = 0;
    }

    float lo, hi; upk2(acc, lo, hi);
    ((float2*)out)[v * 32 + lane] = make_float2(fmaxf(lo, 0.f), fmaxf(hi, 0.f));
}

// ---------------------------------------------------------------------------
extern "C" void kernel_launch(void* const* d_in, const int* in_sizes, int n_in,
                              void* d_out, int out_size)
{
    const float* x_v  = (const float*)d_in[0];
    const float* x_c  = (const float*)d_in[1];
    const float* W1v  = (const float*)d_in[2];
    const float* b1v  = (const float*)d_in[3];
    const float* W2v  = (const float*)d_in[4];
    const float* b2v  = (const float*)d_in[5];
    const float* W1c  = (const float*)d_in[6];
    const float* b1c  = (const float*)d_in[7];
    const float* W2c  = (const float*)d_in[8];
    const float* b2c  = (const float*)d_in[9];
    const int* src_vv = (const int*)d_in[10];
    const int* dst_vv = (const int*)d_in[11];
    const int* src_vc = (const int*)d_in[12];
    const int* dst_vc = (const int*)d_in[13];
    float* out = (float*)d_out;

    const int smem_b = (DD * HH + HH * DD + HH + DD + DD * 33) * (int)sizeof(float)
                     + HH * 33 * (int)sizeof(ull);   // 108544 bytes
    cudaFuncSetAttribute(fused_kernel,
                         cudaFuncAttributeMaxDynamicSharedMemorySize, smem_b);

    // 1. fill (edge slot lists) + vertex MLP + color MLP, one resident wave
    fused_kernel<<<FUSED_GRID, 256, smem_b>>>(
        x_v, x_c, W1v, b1v, W2v, b2v, W1c, b1c, W2c, b2c,
        src_vv, dst_vv, src_vc, dst_vc);

    // 2. gather + residual + relu (+ counter self-clean)
    gather_kernel<<<NN / 8, 256>>>(x_v, out);
}

// round 7
// speedup vs baseline: 1.3487x; 1.3487x over previous
#include <cuda_runtime.h>

#define NN  50000
#define NC  256
#define DD  64
#define HH  128
#define EVV 800000
#define EVC 400000

#define CAPVV 64                  // max stored in-degree (Poisson mean 16)
#define CAPVC 32                  // max stored in-degree (Poisson mean 8)

#define FILL_BLOCKS 128
#define CMLP_BLOCKS 8
#define FUSED_GRID  296           // = 148 SMs * 2 blocks
#define NTILES_V    1563          // ceil(50000/32)

typedef unsigned long long ull;

// ---------------- scratch (device globals; zero-initialized at load) --------
__device__ float g_yv[NN * DD];          // per-vertex messages, 12.8 MB
__device__ float g_yc[NC * DD];          // per-color messages, 64 KB
__device__ int   d_cnt_vv[NN];           // in-degree counters (self-cleaned)
__device__ int   d_cnt_vc[NN];
__device__ int   d_slot_vv[NN * CAPVV];  // padded src lists
__device__ int   d_slot_vc[NN * CAPVC];
__device__ int   d_tile;                 // MLP tile ticket (reset by gather)

// ---------------- f32x2 helpers --------------------------------------------
__device__ __forceinline__ ull pk2(float lo, float hi) {
    ull r; asm("mov.b64 %0, {%1, %2};" : "=l"(r) : "f"(lo), "f"(hi)); return r;
}
__device__ __forceinline__ void upk2(ull v, float& lo, float& hi) {
    asm("mov.b64 {%0, %1}, %2;" : "=f"(lo), "=f"(hi) : "l"(v));
}
__device__ __forceinline__ ull ffma2(ull a, ull b, ull c) {
    ull d; asm("fma.rn.f32x2 %0, %1, %2, %3;" : "=l"(d) : "l"(a), "l"(b), "l"(c)); return d;
}
__device__ __forceinline__ ull fadd2(ull a, ull b) {
    ull d; asm("add.rn.f32x2 %0, %1, %2;" : "=l"(d) : "l"(a), "l"(b)); return d;
}

// ---------------------------------------------------------------------------
// One 32-row MLP tile: Y[row0..row0+31] = relu(X@W1+b1)@W2+b2
// lane = row, warp covers columns; weights broadcast from SMEM; FFMA2.
// Caller guarantees a __syncthreads() happened since last use of xs/hs.
// ---------------------------------------------------------------------------
__device__ __forceinline__ void mlp_tile(
    const float* __restrict__ X, float* __restrict__ Y,
    int row0, int nrows,
    const float* W1s, const float* W2s, const float* b1s, const float* b2s,
    float* xs, ull* hs, int t)
{
    const int lane = t & 31;
    const int warp = t >> 5;

    // load x tile (32 rows x 64) transposed into xs[k][row]
    {
        const int r = t >> 3;       // 0..31
        const int q = t & 7;
        const int row = row0 + r;
#pragma unroll
        for (int h = 0; h < 2; h++) {
            const int q4 = q + 8 * h;        // 0..15
            float4 v = make_float4(0.f, 0.f, 0.f, 0.f);
            if (row < nrows) v = ((const float4*)X)[row * 16 + q4];
            xs[(4 * q4 + 0) * 33 + r] = v.x;
            xs[(4 * q4 + 1) * 33 + r] = v.y;
            xs[(4 * q4 + 2) * 33 + r] = v.z;
            xs[(4 * q4 + 3) * 33 + r] = v.w;
        }
    }
    __syncthreads();

    // phase 1: h = relu(x@W1+b1); warp covers 16 cols
    {
        const int c0 = warp * 16;
        ull acc[8];
#pragma unroll
        for (int p = 0; p < 8; p++)
            acc[p] = *(const ull*)(b1s + c0 + 2 * p);
#pragma unroll 4
        for (int k = 0; k < DD; k++) {
            const float xv = xs[k * 33 + lane];
            const ull xp = pk2(xv, xv);
            const ull* wrow = (const ull*)(W1s + k * HH + c0);
#pragma unroll
            for (int p = 0; p < 8; p++)
                acc[p] = ffma2(wrow[p], xp, acc[p]);
        }
#pragma unroll
        for (int p = 0; p < 8; p++) {
            float lo, hi; upk2(acc[p], lo, hi);
            lo = fmaxf(lo, 0.f); hi = fmaxf(hi, 0.f);
            hs[(c0 + 2 * p + 0) * 33 + lane] = pk2(lo, lo);
            hs[(c0 + 2 * p + 1) * 33 + lane] = pk2(hi, hi);
        }
    }
    __syncthreads();

    // phase 2: y = h@W2+b2; warp covers 8 cols
    {
        const int c0 = warp * 8;
        ull acc[4];
#pragma unroll
        for (int p = 0; p < 4; p++)
            acc[p] = *(const ull*)(b2s + c0 + 2 * p);
#pragma unroll 4
        for (int j = 0; j < HH; j++) {
            const ull hp = hs[j * 33 + lane];
            const ull* wrow = (const ull*)(W2s + j * DD + c0);
#pragma unroll
            for (int p = 0; p < 4; p++)
                acc[p] = ffma2(wrow[p], hp, acc[p]);
        }
        const int row = row0 + lane;
        if (row < nrows) {
            float a0, a1, a2, a3, a4, a5, a6, a7;
            upk2(acc[0], a0, a1); upk2(acc[1], a2, a3);
            upk2(acc[2], a4, a5); upk2(acc[3], a6, a7);
            float4* yp = (float4*)(Y + row * DD + c0);
            yp[0] = make_float4(a0, a1, a2, a3);
            yp[1] = make_float4(a4, a5, a6, a7);
        }
    }
}

__device__ __forceinline__ void load_weights(
    const float* __restrict__ W1, const float* __restrict__ B1,
    const float* __restrict__ W2, const float* __restrict__ B2,
    float* W1s, float* W2s, float* b1s, float* b2s, int t)
{
    const float4* s1 = (const float4*)W1;
    float4* d1 = (float4*)W1s;
    for (int i = t; i < DD * HH / 4; i += 256) d1[i] = s1[i];
    const float4* s2 = (const float4*)W2;
    float4* d2 = (float4*)W2s;
    for (int i = t; i < HH * DD / 4; i += 256) d2[i] = s2[i];
    if (t < HH) b1s[t] = B1[t];
    if (t < DD) b2s[t] = B2[t];
}

// ---------------------------------------------------------------------------
// Fused kernel. Role prologues, then ALL blocks join a dynamic ticket over
// the 1563 vertex-MLP tiles (no idle SM slots after a role finishes):
//   blocks [0,128)   : edge fill prologue
//   blocks [288,296) : color MLP prologue (1 tile each)
//   everyone         : vertex MLP via atomic ticket
// ---------------------------------------------------------------------------
__global__ void __launch_bounds__(256, 2) fused_kernel(
    const float* __restrict__ x_v,
    const float* __restrict__ x_c,
    const float* __restrict__ W1v, const float* __restrict__ b1v,
    const float* __restrict__ W2v, const float* __restrict__ b2v,
    const float* __restrict__ W1c, const float* __restrict__ b1c,
    const float* __restrict__ W2c, const float* __restrict__ b2c,
    const int* __restrict__ src_vv, const int* __restrict__ dst_vv,
    const int* __restrict__ src_vc, const int* __restrict__ dst_vc)
{
    extern __shared__ float sm[];
    float* W1s = sm;                     // [64][128]
    float* W2s = W1s + DD * HH;          // [128][64]
    float* b1s = W2s + HH * DD;          // [128]
    float* b2s = b1s + HH;               // [64]
    float* xs  = b2s + DD;               // [64][33]
    ull*   hs  = (ull*)(xs + DD * 33);   // [128][33]
    __shared__ int s_tile;

    const int t = threadIdx.x;
    const int bid = blockIdx.x;

    // ---- role prologue ----
    if (bid < FILL_BLOCKS) {
        const int g = bid * 256 + t;
        const int stride = FILL_BLOCKS * 256;
        for (int i = g; i < EVV; i += stride) {
            const int d = dst_vv[i];
            const int p = atomicAdd(&d_cnt_vv[d], 1);
            if (p < CAPVV) d_slot_vv[d * CAPVV + p] = src_vv[i];
        }
        for (int i = g; i < EVC; i += stride) {
            const int d = dst_vc[i];
            const int p = atomicAdd(&d_cnt_vc[d], 1);
            if (p < CAPVC) d_slot_vc[d * CAPVC + p] = src_vc[i];
        }
    } else if (bid >= FUSED_GRID - CMLP_BLOCKS) {
        // color MLP: 8 blocks, 1 tile each
        load_weights(W1c, b1c, W2c, b2c, W1s, W2s, b1s, b2s, t);
        __syncthreads();
        mlp_tile(x_c, g_yc, (bid - (FUSED_GRID - CMLP_BLOCKS)) * 32, NC,
                 W1s, W2s, b1s, b2s, xs, hs, t);
        __syncthreads();   // done with smem before reloading vertex weights
    }

    // ---- vertex MLP via dynamic ticket ----
    load_weights(W1v, b1v, W2v, b2v, W1s, W2s, b1s, b2s, t);
    for (;;) {
        __syncthreads();   // weights visible / prev tile buffers free
        if (t == 0) s_tile = atomicAdd(&d_tile, 1);
        __syncthreads();
        const int tile = s_tile;
        if (tile >= NTILES_V) break;
        mlp_tile(x_v, g_yv, tile * 32, NN, W1s, W2s, b1s, b2s, xs, hs, t);
    }
}

// ---------------------------------------------------------------------------
// Gather: 2 vertices per warp, lane = float4 chunk (LDG.128).
//   half = lane>>4 selects the vertex, q = lane&15 the 16B chunk.
// Slot indices are half-warp-uniform broadcast loads (no shfl).
// Accumulate with packed f32x2 adds; out = relu(x + sums); self-clean
// counters and reset the MLP tile ticket for the next graph replay.
// ---------------------------------------------------------------------------
__global__ void __launch_bounds__(256) gather_kernel(
    const float* __restrict__ x_v, float* __restrict__ out)
{
    const int gwarp = (blockIdx.x * 256 + threadIdx.x) >> 5;  // 0..24999
    const int lane = threadIdx.x & 31;
    const int half = lane >> 4;
    const int q = lane & 15;
    const int v = gwarp * 2 + half;                            // 0..49999

    float4 a4 = ((const float4*)x_v)[v * 16 + q];
    ull acc_lo = pk2(a4.x, a4.y);
    ull acc_hi = pk2(a4.z, a4.w);

    // vertex->vertex in-edges (y_v L2-resident; streaming loads)
    {
        const int cnt = min(d_cnt_vv[v], CAPVV);
        const int* slots = d_slot_vv + v * CAPVV;
        const ulonglong2* yv = (const ulonglong2*)g_yv;
        int i = 0;
        for (; i + 8 <= cnt; i += 8) {
            ulonglong2 tt[8];
#pragma unroll
            for (int j = 0; j < 8; j++) {
                const int s = slots[i + j];            // uniform per half-warp
                tt[j] = __ldcs(yv + s * 16 + q);
            }
#pragma unroll
            for (int j = 0; j < 8; j++) {
                acc_lo = fadd2(acc_lo, tt[j].x);
                acc_hi = fadd2(acc_hi, tt[j].y);
            }
        }
        for (; i < cnt; i++) {
            const ulonglong2 tt = __ldcs(yv + slots[i] * 16 + q);
            acc_lo = fadd2(acc_lo, tt.x);
            acc_hi = fadd2(acc_hi, tt.y);
        }
    }

    // color->vertex in-edges (y_c is 64 KB, L1-hot)
    {
        const int cnt = min(d_cnt_vc[v], CAPVC);
        const int* slots = d_slot_vc + v * CAPVC;
        const ulonglong2* yc = (const ulonglong2*)g_yc;
        int i = 0;
        for (; i + 4 <= cnt; i += 4) {
            ulonglong2 tt[4];
#pragma unroll
            for (int j = 0; j < 4; j++) {
                const int s = slots[i + j];
                tt[j] = __ldg(yc + s * 16 + q);
            }
#pragma unroll
            for (int j = 0; j < 4; j++) {
                acc_lo = fadd2(acc_lo, tt[j].x);
                acc_hi = fadd2(acc_hi, tt[j].y);
            }
        }
        for (; i < cnt; i++) {
            const ulonglong2 tt = __ldg(yc + slots[i] * 16 + q);
            acc_lo = fadd2(acc_lo, tt.x);
            acc_hi = fadd2(acc_hi, tt.y);
        }
    }

    // self-clean per-replay state
    if (q == 0) {
        d_cnt_vv[v] = 0;
        d_cnt_vc[v] = 0;
    }
    if (blockIdx.x == 0 && threadIdx.x == 0) d_tile = 0;

    float r0, r1, r2, r3;
    upk2(acc_lo, r0, r1); upk2(acc_hi, r2, r3);
    ((float4*)out)[v * 16 + q] = make_float4(fmaxf(r0, 0.f), fmaxf(r1, 0.f),
                                             fmaxf(r2, 0.f), fmaxf(r3, 0.f));
}

// ---------------------------------------------------------------------------
extern "C" void kernel_launch(void* const* d_in, const int* in_sizes, int n_in,
                              void* d_out, int out_size)
{
    const float* x_v  = (const float*)d_in[0];
    const float* x_c  = (const float*)d_in[1];
    const float* W1v  = (const float*)d_in[2];
    const float* b1v  = (const float*)d_in[3];
    const float* W2v  = (const float*)d_in[4];
    const float* b2v  = (const float*)d_in[5];
    const float* W1c  = (const float*)d_in[6];
    const float* b1c  = (const float*)d_in[7];
    const float* W2c  = (const float*)d_in[8];
    const float* b2c  = (const float*)d_in[9];
    const int* src_vv = (const int*)d_in[10];
    const int* dst_vv = (const int*)d_in[11];
    const int* src_vc = (const int*)d_in[12];
    const int* dst_vc = (const int*)d_in[13];
    float* out = (float*)d_out;

    const int smem_b = (DD * HH + HH * DD + HH + DD + DD * 33) * (int)sizeof(float)
                     + HH * 33 * (int)sizeof(ull);   // 108544 bytes
    cudaFuncSetAttribute(fused_kernel,
                         cudaFuncAttributeMaxDynamicSharedMemorySize, smem_b);

    // 1. fill + color MLP + vertex MLP (dynamic ticket), one resident wave
    fused_kernel<<<FUSED_GRID, 256, smem_b>>>(
        x_v, x_c, W1v, b1v, W2v, b2v, W1c, b1c, W2c, b2c,
        src_vv, dst_vv, src_vc, dst_vc);

    // 2. gather + residual + relu (+ state self-clean)
    gather_kernel<<<NN / 16, 256>>>(x_v, out);
}

// round 10
// speedup vs baseline: 1.8831x; 1.3963x over previous
#include <cuda_runtime.h>
#include <cuda_bf16.h>
#include <cstdint>

#define NN  50000
#define NC  256
#define DD  64
#define HH  128
#define EVV 800000
#define EVC 400000

#define CAPVV 64
#define CAPVC 32

#define FILL_BLOCKS 128
#define VTILES 391                 // ceil(50000/128)
#define CTILES 2
#define FUSED_GRID (FILL_BLOCKS + CTILES + VTILES)   // 521

// ---- smem layout (bytes). Row strides chosen so stride/4 mod 32 == 4 ----
// (guarantees conflict-free fragment LDS: bank = 4*row + word_in_row)
#define W1_STRIDE_W 36             // uint32 words per row (64 bf16 + pad)
#define W2_STRIDE_W 68             // uint32 words per row (128 bf16 + pad)
#define SM_W1H 0                   // 128 rows * 144B = 18432
#define SM_W1L 18432
#define SM_W2H 36864               // 64 rows * 272B = 17408
#define SM_W2L 54272
#define SM_B1S 71680               // 512
#define SM_B2S 72192               // 256
#define SM_XH  72448               // 128 rows * 144B = 18432
#define SM_XL  90880
#define SM_TOTAL 109312

typedef unsigned long long ull;

// ---------------- scratch (device globals; zero-initialized) ----------------
__device__ float g_yv[NN * DD];
__device__ float g_yc[NC * DD];
__device__ int   d_cnt_vv[NN];
__device__ int   d_cnt_vc[NN];
__device__ int   d_slot_vv[NN * CAPVV];
__device__ int   d_slot_vc[NN * CAPVC];

// ---------------- helpers ----------------------------------------------------
__device__ __forceinline__ void bsplit(float v, unsigned short& h, unsigned short& l) {
    __nv_bfloat16 bh = __float2bfloat16(v);
    float r = v - __bfloat162float(bh);
    __nv_bfloat16 bl = __float2bfloat16(r);
    h = __bfloat16_as_ushort(bh);
    l = __bfloat16_as_ushort(bl);
}
// pack {lo_val -> bits[15:0], hi_val -> bits[31:16]} as bf16x2
__device__ __forceinline__ uint32_t pkbf(float hi_val, float lo_val) {
    uint32_t r;
    asm("cvt.rn.bf16x2.f32 %0, %1, %2;" : "=r"(r) : "f"(hi_val), "f"(lo_val));
    return r;
}
__device__ __forceinline__ void mma16816(float* c, const uint32_t* a,
                                         uint32_t b0, uint32_t b1) {
    asm volatile(
        "mma.sync.aligned.m16n8k16.row.col.f32.bf16.bf16.f32 "
        "{%0,%1,%2,%3}, {%4,%5,%6,%7}, {%8,%9}, {%0,%1,%2,%3};"
        : "+f"(c[0]), "+f"(c[1]), "+f"(c[2]), "+f"(c[3])
        : "r"(a[0]), "r"(a[1]), "r"(a[2]), "r"(a[3]), "r"(b0), "r"(b1));
}
__device__ __forceinline__ ull pk2(float lo, float hi) {
    ull r; asm("mov.b64 %0, {%1, %2};" : "=l"(r) : "f"(lo), "f"(hi)); return r;
}
__device__ __forceinline__ void upk2(ull v, float& lo, float& hi) {
    asm("mov.b64 {%0, %1}, %2;" : "=f"(lo), "=f"(hi) : "l"(v));
}
__device__ __forceinline__ ull fadd2(ull a, ull b) {
    ull d; asm("add.rn.f32x2 %0, %1, %2;" : "=l"(d) : "l"(a), "l"(b)); return d;
}

// ---------------------------------------------------------------------------
// Fused: blocks [0,128) edge fill; remaining 393 blocks = one 128-row MLP
// tile via warp-level bf16 HMMA (3-term split, fp32 accumulate).
// ---------------------------------------------------------------------------
__global__ void __launch_bounds__(256) fused_kernel(
    const float* __restrict__ x_v, const float* __restrict__ x_c,
    const float* __restrict__ W1v, const float* __restrict__ b1v,
    const float* __restrict__ W2v, const float* __restrict__ b2v,
    const float* __restrict__ W1c, const float* __restrict__ b1c,
    const float* __restrict__ W2c, const float* __restrict__ b2c,
    const int* __restrict__ src_vv, const int* __restrict__ dst_vv,
    const int* __restrict__ src_vc, const int* __restrict__ dst_vc)
{
    const int t = threadIdx.x;
    const int bid = blockIdx.x;

    // ---------------- fill role ----------------
    if (bid < FILL_BLOCKS) {
        const int g = bid * 256 + t;
        const int stride = FILL_BLOCKS * 256;
        for (int i = g; i < EVV; i += stride) {
            const int d = dst_vv[i];
            const int p = atomicAdd(&d_cnt_vv[d], 1);
            if (p < CAPVV) d_slot_vv[d * CAPVV + p] = src_vv[i];
        }
        for (int i = g; i < EVC; i += stride) {
            const int d = dst_vc[i];
            const int p = atomicAdd(&d_cnt_vc[d], 1);
            if (p < CAPVC) d_slot_vc[d * CAPVC + p] = src_vc[i];
        }
        return;
    }

    // ---------------- MLP tile role ----------------
    extern __shared__ char smem[];
    unsigned short* W1h = (unsigned short*)(smem + SM_W1H);
    unsigned short* W1l = (unsigned short*)(smem + SM_W1L);
    unsigned short* W2h = (unsigned short*)(smem + SM_W2H);
    unsigned short* W2l = (unsigned short*)(smem + SM_W2L);
    float* b1s = (float*)(smem + SM_B1S);
    float* b2s = (float*)(smem + SM_B2S);
    unsigned short* Xh = (unsigned short*)(smem + SM_XH);
    unsigned short* Xl = (unsigned short*)(smem + SM_XL);

    const int tile = bid - FILL_BLOCKS;
    const bool is_color = (tile < CTILES);
    const float* X  = is_color ? x_c : x_v;
    float*       Y  = is_color ? g_yc : g_yv;
    const float* W1 = is_color ? W1c : W1v;
    const float* W2 = is_color ? W2c : W2v;
    const float* B1 = is_color ? b1c : b1v;
    const float* B2 = is_color ? b2c : b2v;
    const int row0 = is_color ? tile * 128 : (tile - CTILES) * 128;
    const int nrows = is_color ? NC : NN;
    const int rem = min(128, nrows - row0);

    const int warp = t >> 5;
    const int lane = t & 31;
    const int qr = lane >> 2;     // 0..7
    const int qc = lane & 3;      // 0..3

    // ---- prologue: split weights into transposed padded smem images ----
    {
        // W1 [64 k][128 n] -> image [n][k]
        const int n = t >> 1;
        const int kh = (t & 1) * 32;
#pragma unroll 8
        for (int i = 0; i < 32; i++) {
            const int k = kh + i;
            unsigned short h, l;
            bsplit(W1[k * HH + n], h, l);
            W1h[n * (2 * W1_STRIDE_W) + k] = h;
            W1l[n * (2 * W1_STRIDE_W) + k] = l;
        }
        // W2 [128 j][64 c] -> image [c][j]
        const int c = t >> 2;
        const int jh = (t & 3) * 32;
#pragma unroll 8
        for (int i = 0; i < 32; i++) {
            const int j = jh + i;
            unsigned short h, l;
            bsplit(W2[j * DD + c], h, l);
            W2h[c * (2 * W2_STRIDE_W) + j] = h;
            W2l[c * (2 * W2_STRIDE_W) + j] = l;
        }
        if (t < HH) b1s[t] = B1[t];
        if (t < DD) b2s[t] = B2[t];
        // x tile: warp loads its 16 rows, split -> images [row][k]
        const int rl = warp * 16 + (lane >> 1);      // 0..127
        const int colh = (lane & 1) * 32;
        float xv[32];
        if (rl < rem) {
            const float4* xp = (const float4*)(X + (size_t)(row0 + rl) * DD + colh);
#pragma unroll
            for (int i = 0; i < 8; i++) ((float4*)xv)[i] = xp[i];
        } else {
#pragma unroll
            for (int i = 0; i < 32; i++) xv[i] = 0.0f;
        }
#pragma unroll
        for (int i = 0; i < 32; i++) {
            unsigned short h, l;
            bsplit(xv[i], h, l);
            Xh[rl * (2 * W1_STRIDE_W) + colh + i] = h;
            Xl[rl * (2 * W1_STRIDE_W) + colh + i] = l;
        }
    }
    __syncthreads();

    const uint32_t* Xh32 = (const uint32_t*)Xh;
    const uint32_t* Xl32 = (const uint32_t*)Xl;
    const uint32_t* W1h32 = (const uint32_t*)W1h;
    const uint32_t* W1l32 = (const uint32_t*)W1l;
    const uint32_t* W2h32 = (const uint32_t*)W2h;
    const uint32_t* W2l32 = (const uint32_t*)W2l;

    // ---- layer 1: acc[16][4] = X(128x64) @ W1(64x128), warp stripe 16 rows
    float acc[16][4];
#pragma unroll
    for (int nt = 0; nt < 16; nt++)
#pragma unroll
        for (int i = 0; i < 4; i++) acc[nt][i] = 0.0f;

    const int arow = warp * 16 + qr;
#pragma unroll
    for (int kb = 0; kb < 4; kb++) {
        const int aw = kb * 8 + qc;
        uint32_t ah[4], al[4];
        ah[0] = Xh32[arow * W1_STRIDE_W + aw];
        ah[1] = Xh32[(arow + 8) * W1_STRIDE_W + aw];
        ah[2] = Xh32[arow * W1_STRIDE_W + aw + 4];
        ah[3] = Xh32[(arow + 8) * W1_STRIDE_W + aw + 4];
        al[0] = Xl32[arow * W1_STRIDE_W + aw];
        al[1] = Xl32[(arow + 8) * W1_STRIDE_W + aw];
        al[2] = Xl32[arow * W1_STRIDE_W + aw + 4];
        al[3] = Xl32[(arow + 8) * W1_STRIDE_W + aw + 4];
#pragma unroll
        for (int nt = 0; nt < 16; nt++) {
            const int bw = (nt * 8 + qr) * W1_STRIDE_W + kb * 8 + qc;
            const uint32_t bh0 = W1h32[bw], bh1 = W1h32[bw + 4];
            const uint32_t bl0 = W1l32[bw], bl1 = W1l32[bw + 4];
            mma16816(acc[nt], ah, bh0, bh1);
            mma16816(acc[nt], ah, bl0, bl1);
            mma16816(acc[nt], al, bh0, bh1);
        }
    }

    // ---- epilogue 1 (in registers): h = relu(acc + b1), split -> layer2 A
    uint32_t a2h[16][2], a2l[16][2];
#pragma unroll
    for (int nt = 0; nt < 16; nt++) {
        const int cn = nt * 8 + 2 * qc;
        const float2 bb = *(const float2*)(b1s + cn);
        const float h0 = fmaxf(acc[nt][0] + bb.x, 0.0f);
        const float h1 = fmaxf(acc[nt][1] + bb.y, 0.0f);
        const float h2 = fmaxf(acc[nt][2] + bb.x, 0.0f);
        const float h3 = fmaxf(acc[nt][3] + bb.y, 0.0f);
        const uint32_t p01 = pkbf(h1, h0);
        const uint32_t p23 = pkbf(h3, h2);
        a2h[nt][0] = p01;
        a2h[nt][1] = p23;
        const float r0 = h0 - __uint_as_float(p01 << 16);
        const float r1 = h1 - __uint_as_float(p01 & 0xFFFF0000u);
        const float r2 = h2 - __uint_as_float(p23 << 16);
        const float r3 = h3 - __uint_as_float(p23 & 0xFFFF0000u);
        a2l[nt][0] = pkbf(r1, r0);
        a2l[nt][1] = pkbf(r3, r2);
    }

    // ---- layer 2: acc2[8][4] = H(128x128) @ W2(128x64)
    float acc2[8][4];
#pragma unroll
    for (int nt = 0; nt < 8; nt++)
#pragma unroll
        for (int i = 0; i < 4; i++) acc2[nt][i] = 0.0f;

#pragma unroll
    for (int kb = 0; kb < 8; kb++) {
        uint32_t ah[4], al[4];
        ah[0] = a2h[2 * kb][0];     ah[1] = a2h[2 * kb][1];
        ah[2] = a2h[2 * kb + 1][0]; ah[3] = a2h[2 * kb + 1][1];
        al[0] = a2l[2 * kb][0];     al[1] = a2l[2 * kb][1];
        al[2] = a2l[2 * kb + 1][0]; al[3] = a2l[2 * kb + 1][1];
#pragma unroll
        for (int nt = 0; nt < 8; nt++) {
            const int bw = (nt * 8 + qr) * W2_STRIDE_W + kb * 8 + qc;
            const uint32_t bh0 = W2h32[bw], bh1 = W2h32[bw + 4];
            const uint32_t bl0 = W2l32[bw], bl1 = W2l32[bw + 4];
            mma16816(acc2[nt], ah, bh0, bh1);
            mma16816(acc2[nt], ah, bl0, bl1);
            mma16816(acc2[nt], al, bh0, bh1);
        }
    }

    // ---- epilogue 2: y = acc2 + b2 -> global (float2 stores) ----
    {
        const int rl0 = warp * 16 + qr;
#pragma unroll
        for (int nt = 0; nt < 8; nt++) {
            const int c = nt * 8 + 2 * qc;
            const float2 bb = *(const float2*)(b2s + c);
            if (rl0 < rem) {
                float2 y; y.x = acc2[nt][0] + bb.x; y.y = acc2[nt][1] + bb.y;
                *(float2*)(Y + (size_t)(row0 + rl0) * DD + c) = y;
            }
            if (rl0 + 8 < rem) {
                float2 y; y.x = acc2[nt][2] + bb.x; y.y = acc2[nt][3] + bb.y;
                *(float2*)(Y + (size_t)(row0 + rl0 + 8) * DD + c) = y;
            }
        }
    }
}

// ---------------------------------------------------------------------------
// Gather: 2 vertices per warp, lane = float4 chunk (unchanged from R7).
// ---------------------------------------------------------------------------
__global__ void __launch_bounds__(256) gather_kernel(
    const float* __restrict__ x_v, float* __restrict__ out)
{
    const int gwarp = (blockIdx.x * 256 + threadIdx.x) >> 5;
    const int lane = threadIdx.x & 31;
    const int half = lane >> 4;
    const int q = lane & 15;
    const int v = gwarp * 2 + half;

    float4 a4 = ((const float4*)x_v)[v * 16 + q];
    ull acc_lo = pk2(a4.x, a4.y);
    ull acc_hi = pk2(a4.z, a4.w);

    {
        const int cnt = min(d_cnt_vv[v], CAPVV);
        const int* slots = d_slot_vv + v * CAPVV;
        const ulonglong2* yv = (const ulonglong2*)g_yv;
        int i = 0;
        for (; i + 8 <= cnt; i += 8) {
            ulonglong2 tt[8];
#pragma unroll
            for (int j = 0; j < 8; j++) tt[j] = __ldcs(yv + slots[i + j] * 16 + q);
#pragma unroll
            for (int j = 0; j < 8; j++) {
                acc_lo = fadd2(acc_lo, tt[j].x);
                acc_hi = fadd2(acc_hi, tt[j].y);
            }
        }
        for (; i < cnt; i++) {
            const ulonglong2 tt = __ldcs(yv + slots[i] * 16 + q);
            acc_lo = fadd2(acc_lo, tt.x);
            acc_hi = fadd2(acc_hi, tt.y);
        }
    }
    {
        const int cnt = min(d_cnt_vc[v], CAPVC);
        const int* slots = d_slot_vc + v * CAPVC;
        const ulonglong2* yc = (const ulonglong2*)g_yc;
        int i = 0;
        for (; i + 4 <= cnt; i += 4) {
            ulonglong2 tt[4];
#pragma unroll
            for (int j = 0; j < 4; j++) tt[j] = __ldg(yc + slots[i + j] * 16 + q);
#pragma unroll
            for (int j = 0; j < 4; j++) {
                acc_lo = fadd2(acc_lo, tt[j].x);
                acc_hi = fadd2(acc_hi, tt[j].y);
            }
        }
        for (; i < cnt; i++) {
            const ulonglong2 tt = __ldg(yc + slots[i] * 16 + q);
            acc_lo = fadd2(acc_lo, tt.x);
            acc_hi = fadd2(acc_hi, tt.y);
        }
    }

    if (q == 0) { d_cnt_vv[v] = 0; d_cnt_vc[v] = 0; }

    float r0, r1, r2, r3;
    upk2(acc_lo, r0, r1); upk2(acc_hi, r2, r3);
    ((float4*)out)[v * 16 + q] = make_float4(fmaxf(r0, 0.f), fmaxf(r1, 0.f),
                                             fmaxf(r2, 0.f), fmaxf(r3, 0.f));
}

// ---------------------------------------------------------------------------
extern "C" void kernel_launch(void* const* d_in, const int* in_sizes, int n_in,
                              void* d_out, int out_size)
{
    const float* x_v  = (const float*)d_in[0];
    const float* x_c  = (const float*)d_in[1];
    const float* W1v  = (const float*)d_in[2];
    const float* b1v  = (const float*)d_in[3];
    const float* W2v  = (const float*)d_in[4];
    const float* b2v  = (const float*)d_in[5];
    const float* W1c  = (const float*)d_in[6];
    const float* b1c  = (const float*)d_in[7];
    const float* W2c  = (const float*)d_in[8];
    const float* b2c  = (const float*)d_in[9];
    const int* src_vv = (const int*)d_in[10];
    const int* dst_vv = (const int*)d_in[11];
    const int* src_vc = (const int*)d_in[12];
    const int* dst_vc = (const int*)d_in[13];
    float* out = (float*)d_out;

    cudaFuncSetAttribute(fused_kernel,
                         cudaFuncAttributeMaxDynamicSharedMemorySize, SM_TOTAL);

    // 1. fill + HMMA MLP tiles (vertex + color), one launch
    fused_kernel<<<FUSED_GRID, 256, SM_TOTAL>>>(
        x_v, x_c, W1v, b1v, W2v, b2v, W1c, b1c, W2c, b2c,
        src_vv, dst_vv, src_vc, dst_vc);

    // 2. gather + residual + relu (+ counter self-clean)
    gather_kernel<<<NN / 16, 256>>>(x_v, out);
}

// round 11
// speedup vs baseline: 2.0284x; 1.0771x over previous
#include <cuda_runtime.h>
#include <cuda_bf16.h>
#include <cstdint>

#define NN  50000
#define NC  256
#define DD  64
#define HH  128
#define EVV 800000
#define EVC 400000

#define CAPVV 64
#define CAPVC 32

#define VTILES 391                 // ceil(50000/128)
#define CTILES 2
#define FUSED_GRID (VTILES + CTILES)   // 393

// ---- smem layout (bytes). Row strides chosen so stride/4 mod 32 == 4 ----
#define W1_STRIDE_W 36             // uint32 words per row (64 bf16 + pad)
#define W2_STRIDE_W 68             // uint32 words per row (128 bf16 + pad)
#define SM_W1H 0                   // 128 rows * 144B = 18432
#define SM_W1L 18432
#define SM_W2H 36864               // 64 rows * 272B = 17408
#define SM_W2L 54272
#define SM_B1S 71680               // 512
#define SM_B2S 72192               // 256
#define WBLOB  72448               // weight image size (everything above)
#define SM_XH  72448               // 128 rows * 144B = 18432
#define SM_XL  90880
#define SM_TOTAL 109312

typedef unsigned long long ull;

// ---------------- scratch (device globals; zero-initialized) ----------------
__device__ float g_yv[NN * DD];
__device__ float g_yc[NC * DD];
__device__ int   d_cnt_vv[NN];
__device__ int   d_cnt_vc[NN];
__device__ int   d_slot_vv[NN * CAPVV];
__device__ int   d_slot_vc[NN * CAPVC];
__device__ __align__(16) unsigned char g_wblob[2][WBLOB];  // smem-image weights

// ---------------- helpers ----------------------------------------------------
__device__ __forceinline__ void bsplit(float v, unsigned short& h, unsigned short& l) {
    __nv_bfloat16 bh = __float2bfloat16(v);
    float r = v - __bfloat162float(bh);
    __nv_bfloat16 bl = __float2bfloat16(r);
    h = __bfloat16_as_ushort(bh);
    l = __bfloat16_as_ushort(bl);
}
__device__ __forceinline__ uint32_t pkbf(float hi_val, float lo_val) {
    uint32_t r;
    asm("cvt.rn.bf16x2.f32 %0, %1, %2;" : "=r"(r) : "f"(hi_val), "f"(lo_val));
    return r;
}
__device__ __forceinline__ void mma16816(float* c, const uint32_t* a,
                                         uint32_t b0, uint32_t b1) {
    asm volatile(
        "mma.sync.aligned.m16n8k16.row.col.f32.bf16.bf16.f32 "
        "{%0,%1,%2,%3}, {%4,%5,%6,%7}, {%8,%9}, {%0,%1,%2,%3};"
        : "+f"(c[0]), "+f"(c[1]), "+f"(c[2]), "+f"(c[3])
        : "r"(a[0]), "r"(a[1]), "r"(a[2]), "r"(a[3]), "r"(b0), "r"(b1));
}
__device__ __forceinline__ ull pk2(float lo, float hi) {
    ull r; asm("mov.b64 %0, {%1, %2};" : "=l"(r) : "f"(lo), "f"(hi)); return r;
}
__device__ __forceinline__ void upk2(ull v, float& lo, float& hi) {
    asm("mov.b64 {%0, %1}, %2;" : "=f"(lo), "=f"(hi) : "l"(v));
}
__device__ __forceinline__ ull fadd2(ull a, ull b) {
    ull d; asm("add.rn.f32x2 %0, %1, %2;" : "=l"(d) : "l"(a), "l"(b)); return d;
}

// ---------------------------------------------------------------------------
// Prep: build the smem-image weight blobs (split bf16, transposed, padded).
// grid 64: net = bid&1, chunk = bid>>1 (32 chunks).
// ---------------------------------------------------------------------------
__global__ void __launch_bounds__(256) prep_kernel(
    const float* __restrict__ W1v, const float* __restrict__ b1v,
    const float* __restrict__ W2v, const float* __restrict__ b2v,
    const float* __restrict__ W1c, const float* __restrict__ b1c,
    const float* __restrict__ W2c, const float* __restrict__ b2c)
{
    const int net = blockIdx.x & 1;
    const int chunk = blockIdx.x >> 1;
    const int t = threadIdx.x;
    const float* W1 = net ? W1c : W1v;
    const float* W2 = net ? W2c : W2v;
    unsigned char* blob = g_wblob[net];
    unsigned short* W1h = (unsigned short*)(blob + SM_W1H);
    unsigned short* W1l = (unsigned short*)(blob + SM_W1L);
    unsigned short* W2h = (unsigned short*)(blob + SM_W2H);
    unsigned short* W2l = (unsigned short*)(blob + SM_W2L);

    // W1 [64 k][128 n] -> image [n][k]; 4 n-rows per chunk
    {
        const int n = chunk * 4 + (t >> 6);
        const int k = t & 63;
        unsigned short h, l;
        bsplit(W1[k * HH + n], h, l);
        W1h[n * (2 * W1_STRIDE_W) + k] = h;
        W1l[n * (2 * W1_STRIDE_W) + k] = l;
    }
    // W2 [128 j][64 c] -> image [c][j]; 2 c-rows per chunk
    {
        const int c = chunk * 2 + (t >> 7);
        const int j = t & 127;
        unsigned short h, l;
        bsplit(W2[j * DD + c], h, l);
        W2h[c * (2 * W2_STRIDE_W) + j] = h;
        W2l[c * (2 * W2_STRIDE_W) + j] = l;
    }
    if (chunk == 0) {
        const float* B1 = net ? b1c : b1v;
        const float* B2 = net ? b2c : b2v;
        if (t < HH) ((float*)(blob + SM_B1S))[t] = B1[t];
        if (t < DD) ((float*)(blob + SM_B2S))[t] = B2[t];
    }
}

// ---------------------------------------------------------------------------
// Fused: every block does (a) a strided slice of edge fill, then (b) one
// 128-row MLP tile via warp-level bf16 HMMA (3-term split, fp32 accumulate).
// ---------------------------------------------------------------------------
__global__ void __launch_bounds__(256) fused_kernel(
    const float* __restrict__ x_v, const float* __restrict__ x_c,
    const int* __restrict__ src_vv, const int* __restrict__ dst_vv,
    const int* __restrict__ src_vc, const int* __restrict__ dst_vc)
{
    const int t = threadIdx.x;
    const int bid = blockIdx.x;

    // ---------------- fill slice (all blocks) ----------------
    {
        const int g = bid * 256 + t;
        const int stride = FUSED_GRID * 256;
        for (int i = g; i < EVV; i += stride) {
            const int d = dst_vv[i];
            const int p = atomicAdd(&d_cnt_vv[d], 1);
            if (p < CAPVV) d_slot_vv[d * CAPVV + p] = src_vv[i];
        }
        for (int i = g; i < EVC; i += stride) {
            const int d = dst_vc[i];
            const int p = atomicAdd(&d_cnt_vc[d], 1);
            if (p < CAPVC) d_slot_vc[d * CAPVC + p] = src_vc[i];
        }
    }

    // ---------------- MLP tile role ----------------
    extern __shared__ char smem[];
    const int tile = bid;
    const bool is_color = (tile < CTILES);
    const float* X  = is_color ? x_c : x_v;
    float*       Y  = is_color ? g_yc : g_yv;
    const int row0 = is_color ? tile * 128 : (tile - CTILES) * 128;
    const int nrows = is_color ? NC : NN;
    const int rem = min(128, nrows - row0);

    const int warp = t >> 5;
    const int lane = t & 31;
    const int qr = lane >> 2;
    const int qc = lane & 3;

    // coalesced copy of the pre-built weight image (L2-hot)
    {
        const float4* src = (const float4*)g_wblob[is_color ? 1 : 0];
        float4* dst = (float4*)smem;
#pragma unroll
        for (int i = 0; i < WBLOB / 16 / 256 + 1; i++) {
            const int idx = i * 256 + t;
            if (idx < WBLOB / 16) dst[idx] = src[idx];
        }
    }
    // x tile: warp loads its 16 rows, split -> images [row][k]
    {
        unsigned short* Xh = (unsigned short*)(smem + SM_XH);
        unsigned short* Xl = (unsigned short*)(smem + SM_XL);
        const int rl = warp * 16 + (lane >> 1);
        const int colh = (lane & 1) * 32;
        float xv[32];
        if (rl < rem) {
            const float4* xp = (const float4*)(X + (size_t)(row0 + rl) * DD + colh);
#pragma unroll
            for (int i = 0; i < 8; i++) ((float4*)xv)[i] = xp[i];
        } else {
#pragma unroll
            for (int i = 0; i < 32; i++) xv[i] = 0.0f;
        }
#pragma unroll
        for (int i = 0; i < 32; i++) {
            unsigned short h, l;
            bsplit(xv[i], h, l);
            Xh[rl * (2 * W1_STRIDE_W) + colh + i] = h;
            Xl[rl * (2 * W1_STRIDE_W) + colh + i] = l;
        }
    }
    __syncthreads();

    const uint32_t* Xh32 = (const uint32_t*)(smem + SM_XH);
    const uint32_t* Xl32 = (const uint32_t*)(smem + SM_XL);
    const uint32_t* W1h32 = (const uint32_t*)(smem + SM_W1H);
    const uint32_t* W1l32 = (const uint32_t*)(smem + SM_W1L);
    const uint32_t* W2h32 = (const uint32_t*)(smem + SM_W2H);
    const uint32_t* W2l32 = (const uint32_t*)(smem + SM_W2L);
    const float* b1s = (const float*)(smem + SM_B1S);
    const float* b2s = (const float*)(smem + SM_B2S);

    // ---- layer 1: acc[16][4] = X(128x64) @ W1(64x128), warp stripe 16 rows
    float acc[16][4];
#pragma unroll
    for (int nt = 0; nt < 16; nt++)
#pragma unroll
        for (int i = 0; i < 4; i++) acc[nt][i] = 0.0f;

    const int arow = warp * 16 + qr;
#pragma unroll
    for (int kb = 0; kb < 4; kb++) {
        const int aw = kb * 8 + qc;
        uint32_t ah[4], al[4];
        ah[0] = Xh32[arow * W1_STRIDE_W + aw];
        ah[1] = Xh32[(arow + 8) * W1_STRIDE_W + aw];
        ah[2] = Xh32[arow * W1_STRIDE_W + aw + 4];
        ah[3] = Xh32[(arow + 8) * W1_STRIDE_W + aw + 4];
        al[0] = Xl32[arow * W1_STRIDE_W + aw];
        al[1] = Xl32[(arow + 8) * W1_STRIDE_W + aw];
        al[2] = Xl32[arow * W1_STRIDE_W + aw + 4];
        al[3] = Xl32[(arow + 8) * W1_STRIDE_W + aw + 4];
#pragma unroll
        for (int nt = 0; nt < 16; nt++) {
            const int bw = (nt * 8 + qr) * W1_STRIDE_W + kb * 8 + qc;
            const uint32_t bh0 = W1h32[bw], bh1 = W1h32[bw + 4];
            const uint32_t bl0 = W1l32[bw], bl1 = W1l32[bw + 4];
            mma16816(acc[nt], ah, bh0, bh1);
            mma16816(acc[nt], ah, bl0, bl1);
            mma16816(acc[nt], al, bh0, bh1);
        }
    }

    // ---- epilogue 1 (in registers): h = relu(acc + b1), split -> layer2 A
    uint32_t a2h[16][2], a2l[16][2];
#pragma unroll
    for (int nt = 0; nt < 16; nt++) {
        const int cn = nt * 8 + 2 * qc;
        const float2 bb = *(const float2*)(b1s + cn);
        const float h0 = fmaxf(acc[nt][0] + bb.x, 0.0f);
        const float h1 = fmaxf(acc[nt][1] + bb.y, 0.0f);
        const float h2 = fmaxf(acc[nt][2] + bb.x, 0.0f);
        const float h3 = fmaxf(acc[nt][3] + bb.y, 0.0f);
        const uint32_t p01 = pkbf(h1, h0);
        const uint32_t p23 = pkbf(h3, h2);
        a2h[nt][0] = p01;
        a2h[nt][1] = p23;
        const float r0 = h0 - __uint_as_float(p01 << 16);
        const float r1 = h1 - __uint_as_float(p01 & 0xFFFF0000u);
        const float r2 = h2 - __uint_as_float(p23 << 16);
        const float r3 = h3 - __uint_as_float(p23 & 0xFFFF0000u);
        a2l[nt][0] = pkbf(r1, r0);
        a2l[nt][1] = pkbf(r3, r2);
    }

    // ---- layer 2: acc2[8][4] = H(128x128) @ W2(128x64)
    float acc2[8][4];
#pragma unroll
    for (int nt = 0; nt < 8; nt++)
#pragma unroll
        for (int i = 0; i < 4; i++) acc2[nt][i] = 0.0f;

#pragma unroll
    for (int kb = 0; kb < 8; kb++) {
        uint32_t ah[4], al[4];
        ah[0] = a2h[2 * kb][0];     ah[1] = a2h[2 * kb][1];
        ah[2] = a2h[2 * kb + 1][0]; ah[3] = a2h[2 * kb + 1][1];
        al[0] = a2l[2 * kb][0];     al[1] = a2l[2 * kb][1];
        al[2] = a2l[2 * kb + 1][0]; al[3] = a2l[2 * kb + 1][1];
#pragma unroll
        for (int nt = 0; nt < 8; nt++) {
            const int bw = (nt * 8 + qr) * W2_STRIDE_W + kb * 8 + qc;
            const uint32_t bh0 = W2h32[bw], bh1 = W2h32[bw + 4];
            const uint32_t bl0 = W2l32[bw], bl1 = W2l32[bw + 4];
            mma16816(acc2[nt], ah, bh0, bh1);
            mma16816(acc2[nt], ah, bl0, bl1);
            mma16816(acc2[nt], al, bh0, bh1);
        }
    }

    // ---- epilogue 2: y = acc2 + b2 -> global (float2 stores) ----
    {
        const int rl0 = warp * 16 + qr;
#pragma unroll
        for (int nt = 0; nt < 8; nt++) {
            const int c = nt * 8 + 2 * qc;
            const float2 bb = *(const float2*)(b2s + c);
            if (rl0 < rem) {
                float2 y; y.x = acc2[nt][0] + bb.x; y.y = acc2[nt][1] + bb.y;
                *(float2*)(Y + (size_t)(row0 + rl0) * DD + c) = y;
            }
            if (rl0 + 8 < rem) {
                float2 y; y.x = acc2[nt][2] + bb.x; y.y = acc2[nt][3] + bb.y;
                *(float2*)(Y + (size_t)(row0 + rl0 + 8) * DD + c) = y;
            }
        }
    }
}

// ---------------------------------------------------------------------------
// Gather: 2 vertices per warp, lane = float4 chunk; int4 slot loads.
// ---------------------------------------------------------------------------
__global__ void __launch_bounds__(256) gather_kernel(
    const float* __restrict__ x_v, float* __restrict__ out)
{
    const int gwarp = (blockIdx.x * 256 + threadIdx.x) >> 5;
    const int lane = threadIdx.x & 31;
    const int half = lane >> 4;
    const int q = lane & 15;
    const int v = gwarp * 2 + half;

    float4 a4 = ((const float4*)x_v)[v * 16 + q];
    ull acc_lo = pk2(a4.x, a4.y);
    ull acc_hi = pk2(a4.z, a4.w);

    // vertex->vertex in-edges (y_v L2-resident)
    {
        const int cnt = min(d_cnt_vv[v], CAPVV);
        const int* slots = d_slot_vv + v * CAPVV;
        const int4* slots4 = (const int4*)slots;
        const ulonglong2* yv = (const ulonglong2*)g_yv;
        int i = 0;
        for (; i + 8 <= cnt; i += 8) {
            const int4 sa = slots4[i >> 2];
            const int4 sb = slots4[(i >> 2) + 1];
            ulonglong2 t0 = __ldcs(yv + sa.x * 16 + q);
            ulonglong2 t1 = __ldcs(yv + sa.y * 16 + q);
            ulonglong2 t2 = __ldcs(yv + sa.z * 16 + q);
            ulonglong2 t3 = __ldcs(yv + sa.w * 16 + q);
            ulonglong2 t4 = __ldcs(yv + sb.x * 16 + q);
            ulonglong2 t5 = __ldcs(yv + sb.y * 16 + q);
            ulonglong2 t6 = __ldcs(yv + sb.z * 16 + q);
            ulonglong2 t7 = __ldcs(yv + sb.w * 16 + q);
            acc_lo = fadd2(acc_lo, t0.x); acc_hi = fadd2(acc_hi, t0.y);
            acc_lo = fadd2(acc_lo, t1.x); acc_hi = fadd2(acc_hi, t1.y);
            acc_lo = fadd2(acc_lo, t2.x); acc_hi = fadd2(acc_hi, t2.y);
            acc_lo = fadd2(acc_lo, t3.x); acc_hi = fadd2(acc_hi, t3.y);
            acc_lo = fadd2(acc_lo, t4.x); acc_hi = fadd2(acc_hi, t4.y);
            acc_lo = fadd2(acc_lo, t5.x); acc_hi = fadd2(acc_hi, t5.y);
            acc_lo = fadd2(acc_lo, t6.x); acc_hi = fadd2(acc_hi, t6.y);
            acc_lo = fadd2(acc_lo, t7.x); acc_hi = fadd2(acc_hi, t7.y);
        }
        for (; i < cnt; i++) {
            const ulonglong2 tt = __ldcs(yv + slots[i] * 16 + q);
            acc_lo = fadd2(acc_lo, tt.x);
            acc_hi = fadd2(acc_hi, tt.y);
        }
    }
    // color->vertex in-edges (y_c is 64 KB, L1-hot)
    {
        const int cnt = min(d_cnt_vc[v], CAPVC);
        const int* slots = d_slot_vc + v * CAPVC;
        const int4* slots4 = (const int4*)slots;
        const ulonglong2* yc = (const ulonglong2*)g_yc;
        int i = 0;
        for (; i + 4 <= cnt; i += 4) {
            const int4 sa = slots4[i >> 2];
            ulonglong2 t0 = __ldg(yc + sa.x * 16 + q);
            ulonglong2 t1 = __ldg(yc + sa.y * 16 + q);
            ulonglong2 t2 = __ldg(yc + sa.z * 16 + q);
            ulonglong2 t3 = __ldg(yc + sa.w * 16 + q);
            acc_lo = fadd2(acc_lo, t0.x); acc_hi = fadd2(acc_hi, t0.y);
            acc_lo = fadd2(acc_lo, t1.x); acc_hi = fadd2(acc_hi, t1.y);
            acc_lo = fadd2(acc_lo, t2.x); acc_hi = fadd2(acc_hi, t2.y);
            acc_lo = fadd2(acc_lo, t3.x); acc_hi = fadd2(acc_hi, t3.y);
        }
        for (; i < cnt; i++) {
            const ulonglong2 tt = __ldg(yc + slots[i] * 16 + q);
            acc_lo = fadd2(acc_lo, tt.x);
            acc_hi = fadd2(acc_hi, tt.y);
        }
    }

    if (q == 0) { d_cnt_vv[v] = 0; d_cnt_vc[v] = 0; }

    float r0, r1, r2, r3;
    upk2(acc_lo, r0, r1); upk2(acc_hi, r2, r3);
    ((float4*)out)[v * 16 + q] = make_float4(fmaxf(r0, 0.f), fmaxf(r1, 0.f),
                                             fmaxf(r2, 0.f), fmaxf(r3, 0.f));
}

// ---------------------------------------------------------------------------
extern "C" void kernel_launch(void* const* d_in, const int* in_sizes, int n_in,
                              void* d_out, int out_size)
{
    const float* x_v  = (const float*)d_in[0];
    const float* x_c  = (const float*)d_in[1];
    const float* W1v  = (const float*)d_in[2];
    const float* b1v  = (const float*)d_in[3];
    const float* W2v  = (const float*)d_in[4];
    const float* b2v  = (const float*)d_in[5];
    const float* W1c  = (const float*)d_in[6];
    const float* b1c  = (const float*)d_in[7];
    const float* W2c  = (const float*)d_in[8];
    const float* b2c  = (const float*)d_in[9];
    const int* src_vv = (const int*)d_in[10];
    const int* dst_vv = (const int*)d_in[11];
    const int* src_vc = (const int*)d_in[12];
    const int* dst_vc = (const int*)d_in[13];
    float* out = (float*)d_out;

    cudaFuncSetAttribute(fused_kernel,
                         cudaFuncAttributeMaxDynamicSharedMemorySize, SM_TOTAL);

    // 1. build smem-image weight blobs (split + transpose + pad)
    prep_kernel<<<64, 256>>>(W1v, b1v, W2v, b2v, W1c, b1c, W2c, b2c);
    // 2. fill slice in every block + HMMA MLP tile per block
    fused_kernel<<<FUSED_GRID, 256, SM_TOTAL>>>(
        x_v, x_c, src_vv, dst_vv, src_vc, dst_vc);
    // 3. gather + residual + relu (+ counter self-clean)
    gather_kernel<<<NN / 16, 256>>>(x_v, out);
}